// round 14
// baseline (speedup 1.0000x reference)
#include <cuda_runtime.h>
#include <cstdint>

#define NB   64
#define NS   512
#define NE   300
#define NH   256
#define NG   1024
#define NT   48
#define NH2  512
#define NTOK (NB*NS)

__device__ float g_z[(size_t)2 * NTOK * NG];
__device__ float g_hout[(size_t)NTOK * NH2];
__device__ float g_probs[(size_t)NTOK * NT];
__device__ float g_hcur[2 * 2 * NB * NH];
__device__ int   g_bar[16];
__device__ float g_res[NB];

__device__ __forceinline__ float fast_sig(float x) { return 1.f / (1.f + __expf(-x)); }
__device__ __forceinline__ float fast_tanh(float x) { return 2.f / (1.f + __expf(-2.f * x)) - 1.f; }

__global__ void init_bar_kernel() {
    if (threadIdx.x < 16) g_bar[threadIdx.x] = 0;
}

// =====================================================================
// K1: embedding gather + input projection GEMM, double-buffered smem.
// Per chunk: issue next chunk's LDGs -> compute current (hides LDG
// latency) -> STS to other buffer -> ONE sync.  64x64 tile, 4x4 micro.
// =====================================================================
#define CHW 4080   // floats per buffer (60*68)
__global__ void __launch_bounds__(256) input_gemm_kernel(
    const int* __restrict__ tok, const float* __restrict__ emb,
    const float* __restrict__ wf, const float* __restrict__ wb,
    const float* __restrict__ bif, const float* __restrict__ bhf,
    const float* __restrict__ bib, const float* __restrict__ bhb)
{
    extern __shared__ float smf[];
    float* Asb = smf;                 // [2][CHW]
    float* Bsb = smf + 2 * CHW;       // [2][CHW]
    __shared__ int ids[64];

    int tid = threadIdx.x;
    int tm = blockIdx.x;
    int tn = blockIdx.y;
    int dir = tn >> 4;
    int rbase = (tn & 15) << 6;
    const float* __restrict__ W = dir ? wb : wf;

    if (tid < 64) ids[tid] = tok[tm * 64 + tid];
    __syncthreads();

    float acc[4][4] = {{0.f}};
    int tx = tid & 15, ty = tid >> 4;
    int fi = tid & 63;
    int fg0 = tid >> 6;

    float4 pa[4], pb[4];
    const float* arow = emb + (size_t)ids[fi] * NE;
    const float* brow = W + (size_t)(rbase + fi) * NE;

    // prologue: fetch + store chunk 0
#pragma unroll
    for (int l = 0; l < 4; ++l) {
        int g = fg0 + l * 4;
        if (g < 15) {
            pa[l] = *(const float4*)(arow + g * 4);
            pb[l] = *(const float4*)(brow + g * 4);
        }
    }
#pragma unroll
    for (int l = 0; l < 4; ++l) {
        int g = fg0 + l * 4;
        if (g < 15) {
            int kk = g * 4;
            Asb[(kk + 0) * 68 + fi] = pa[l].x;
            Asb[(kk + 1) * 68 + fi] = pa[l].y;
            Asb[(kk + 2) * 68 + fi] = pa[l].z;
            Asb[(kk + 3) * 68 + fi] = pa[l].w;
            Bsb[(kk + 0) * 68 + fi] = pb[l].x;
            Bsb[(kk + 1) * 68 + fi] = pb[l].y;
            Bsb[(kk + 2) * 68 + fi] = pb[l].z;
            Bsb[(kk + 3) * 68 + fi] = pb[l].w;
        }
    }
    __syncthreads();

    int p = 0;
    for (int kc = 0; kc < 5; ++kc) {
        // issue next chunk's global loads (latency hidden by compute)
        if (kc < 4) {
            int k0 = (kc + 1) * 60;
#pragma unroll
            for (int l = 0; l < 4; ++l) {
                int g = fg0 + l * 4;
                if (g < 15) {
                    pa[l] = *(const float4*)(arow + k0 + g * 4);
                    pb[l] = *(const float4*)(brow + k0 + g * 4);
                }
            }
        }

        const float* Ap = Asb + p * CHW;
        const float* Bp = Bsb + p * CHW;
#pragma unroll 4
        for (int k = 0; k < 60; ++k) {
            float4 a4 = *(const float4*)(Ap + k * 68 + ty * 4);
            float4 b4 = *(const float4*)(Bp + k * 68 + tx * 4);
            float av[4] = {a4.x, a4.y, a4.z, a4.w};
            float bv[4] = {b4.x, b4.y, b4.z, b4.w};
#pragma unroll
            for (int ii = 0; ii < 4; ++ii)
#pragma unroll
                for (int jj = 0; jj < 4; ++jj)
                    acc[ii][jj] = fmaf(av[ii], bv[jj], acc[ii][jj]);
        }

        if (kc < 4) {
            float* An = Asb + (1 - p) * CHW;
            float* Bn = Bsb + (1 - p) * CHW;
#pragma unroll
            for (int l = 0; l < 4; ++l) {
                int g = fg0 + l * 4;
                if (g < 15) {
                    int kk = g * 4;
                    An[(kk + 0) * 68 + fi] = pa[l].x;
                    An[(kk + 1) * 68 + fi] = pa[l].y;
                    An[(kk + 2) * 68 + fi] = pa[l].z;
                    An[(kk + 3) * 68 + fi] = pa[l].w;
                    Bn[(kk + 0) * 68 + fi] = pb[l].x;
                    Bn[(kk + 1) * 68 + fi] = pb[l].y;
                    Bn[(kk + 2) * 68 + fi] = pb[l].z;
                    Bn[(kk + 3) * 68 + fi] = pb[l].w;
                }
            }
            __syncthreads();
            p ^= 1;
        }
    }

    const float* bi = dir ? bib : bif;
    const float* bh = dir ? bhb : bhf;
    int gcol = rbase + tx * 4;
    float bx = bi[gcol + 0] + bh[gcol + 0];
    float by = bi[gcol + 1] + bh[gcol + 1];
    float bz = bi[gcol + 2] + bh[gcol + 2];
    float bw = bi[gcol + 3] + bh[gcol + 3];

#pragma unroll
    for (int ii = 0; ii < 4; ++ii) {
        int n = tm * 64 + ty * 4 + ii;
        float4 v;
        v.x = acc[ii][0] + bx; v.y = acc[ii][1] + by;
        v.z = acc[ii][2] + bz; v.w = acc[ii][3] + bw;
        *(float4*)&g_z[((size_t)dir * NTOK + n) * NG + gcol] = v;
    }
}
#define GEMM_SMEM (4 * CHW * 4)   // 65280 bytes

// =====================================================================
// K2: persistent BiLSTM recurrence (R13) — relaxed spin + final acquire.
// =====================================================================
__global__ void __launch_bounds__(256) lstm_kernel(
    const float* __restrict__ whhf, const float* __restrict__ whhb)
{
    extern __shared__ float sm[];
    float* Ws  = sm;
    float* hs  = sm + 32768;
    float* red = sm + 34816;

    int bid = blockIdx.x;
    int dir = bid >> 6;
    int bg  = (bid >> 3) & 7;
    int sl  = bid & 7;
    int us  = sl << 5;
    int tid = threadIdx.x;
    int w   = tid >> 5;
    int lane = tid & 31;
    const float* __restrict__ W = dir ? whhb : whhf;

    for (int idx = tid; idx < 32768; idx += 256) {
        int r = idx & 127, k = idx >> 7;
        Ws[idx] = W[(size_t)((r & 3) * NH + us + (r >> 2)) * NH + k];
    }
    for (int i = tid; i < 2048; i += 256) hs[i] = 0.f;
    __syncthreads();

    int b = bg * 8 + w;
    int u = us + lane;
    int bar = dir * 8 + bg;
    int k0 = w * 32;
    const float4* wp = ((const float4*)Ws) + lane;
    int* barp = &g_bar[bar];
    float c = 0.f;

    for (int t = 0; t < NS; ++t) {
        int to = dir ? (NS - 1 - t) : t;

        float acc0[8], acc1[8], acc2[8], acc3[8];
#pragma unroll
        for (int bb = 0; bb < 8; ++bb) { acc0[bb] = acc1[bb] = acc2[bb] = acc3[bb] = 0.f; }

#pragma unroll 4
        for (int kk = 0; kk < 32; ++kk) {
            int k = k0 + kk;
            float4 w4 = wp[k * 32];
#pragma unroll
            for (int bb = 0; bb < 8; ++bb) {
                float h = hs[bb * 256 + k];
                acc0[bb] = fmaf(w4.x, h, acc0[bb]);
                acc1[bb] = fmaf(w4.y, h, acc1[bb]);
                acc2[bb] = fmaf(w4.z, h, acc2[bb]);
                acc3[bb] = fmaf(w4.w, h, acc3[bb]);
            }
        }
#pragma unroll
        for (int bb = 0; bb < 8; ++bb) {
            float4 v; v.x = acc0[bb]; v.y = acc1[bb]; v.z = acc2[bb]; v.w = acc3[bb];
            *(float4*)&red[((w * 8 + bb) * 32 + lane) * 4] = v;
        }

        size_t zb = ((size_t)dir * NTOK + (size_t)b * NS + to) * NG + u;
        float zi = g_z[zb], zf = g_z[zb + 256], zg = g_z[zb + 512], zo = g_z[zb + 768];
        __syncthreads();

        float a0 = zi, a1 = zf, a2 = zg, a3 = zo;
#pragma unroll
        for (int ww = 0; ww < 8; ++ww) {
            float4 p = *(const float4*)&red[((ww * 8 + w) * 32 + lane) * 4];
            a0 += p.x; a1 += p.y; a2 += p.z; a3 += p.w;
        }

        float ig = fast_sig(a0), fg = fast_sig(a1);
        float gg = fast_tanh(a2), og = fast_sig(a3);
        c = fg * c + ig * gg;
        float hn = og * fast_tanh(c);

        int wbuf = t & 1;
        g_hcur[((wbuf * 2 + dir) * NB + b) * NH + u] = hn;

        __syncthreads();
        if (tid == 0) {
            asm volatile("red.release.gpu.global.add.s32 [%0], 1;"
                         :: "l"(barp) : "memory");
        }
        g_hout[((size_t)b * NS + to) * NH2 + dir * NH + u] = hn;

        if (tid == 0) {
            int tgt = 8 * (t + 1);
            int v;
            do {
                asm volatile("ld.relaxed.gpu.global.s32 %0, [%1];"
                             : "=r"(v) : "l"(barp) : "memory");
            } while (v < tgt);
            asm volatile("ld.acquire.gpu.global.s32 %0, [%1];"
                         : "=r"(v) : "l"(barp) : "memory");
        }
        __syncthreads();

        if (t < NS - 1) {
            const float4* src = (const float4*)&g_hcur[((size_t)(wbuf * 2 + dir) * NB + bg * 8) * NH];
            float4* dst = (float4*)hs;
#pragma unroll
            for (int i = tid; i < 512; i += 256) {
                dst[i] = __ldcg(src + i);
            }
            __syncthreads();
        }
    }
}

// =====================================================================
// K3: logits + softmax (R12 — measured good)
// =====================================================================
__global__ void __launch_bounds__(256) logits_kernel(
    const float* __restrict__ wlin, const float* __restrict__ blin)
{
    extern __shared__ float sm[];
    float* ws  = sm;
    float* hsm = sm + 24768;
    int tid = threadIdx.x;
    size_t n0 = (size_t)blockIdx.x * 32;

    for (int i4 = tid; i4 < (NT * NH2) / 4; i4 += 256) {
        int i = i4 * 4;
        float4 v = *(const float4*)&wlin[i];
        *(float4*)&ws[(i >> 9) * 516 + (i & 511)] = v;
    }
    for (int i4 = tid; i4 < (32 * NH2) / 4; i4 += 256) {
        float4 v = *(const float4*)&g_hout[n0 * NH2 + (size_t)i4 * 4];
        *(float4*)&hsm[i4 * 4] = v;
    }
    __syncthreads();

    int pr = tid >> 4, js = tid & 15;
    const float4* h0 = (const float4*)(hsm + (pr * 2 + 0) * NH2);
    const float4* h1 = (const float4*)(hsm + (pr * 2 + 1) * NH2);
    const float4* w0 = (const float4*)(ws + (js * 3 + 0) * 516);
    const float4* w1 = (const float4*)(ws + (js * 3 + 1) * 516);
    const float4* w2 = (const float4*)(ws + (js * 3 + 2) * 516);
    float a0 = 0.f, a1 = 0.f, a2 = 0.f;
    float b0 = 0.f, b1 = 0.f, b2 = 0.f;
#pragma unroll 4
    for (int kk = 0; kk < 128; ++kk) {
        float4 ha = h0[kk];
        float4 hb = h1[kk];
        float4 x0 = w0[kk];
        float4 x1 = w1[kk];
        float4 x2 = w2[kk];
        a0 = fmaf(x0.x, ha.x, a0); a0 = fmaf(x0.y, ha.y, a0);
        a0 = fmaf(x0.z, ha.z, a0); a0 = fmaf(x0.w, ha.w, a0);
        a1 = fmaf(x1.x, ha.x, a1); a1 = fmaf(x1.y, ha.y, a1);
        a1 = fmaf(x1.z, ha.z, a1); a1 = fmaf(x1.w, ha.w, a1);
        a2 = fmaf(x2.x, ha.x, a2); a2 = fmaf(x2.y, ha.y, a2);
        a2 = fmaf(x2.z, ha.z, a2); a2 = fmaf(x2.w, ha.w, a2);
        b0 = fmaf(x0.x, hb.x, b0); b0 = fmaf(x0.y, hb.y, b0);
        b0 = fmaf(x0.z, hb.z, b0); b0 = fmaf(x0.w, hb.w, b0);
        b1 = fmaf(x1.x, hb.x, b1); b1 = fmaf(x1.y, hb.y, b1);
        b1 = fmaf(x1.z, hb.z, b1); b1 = fmaf(x1.w, hb.w, b1);
        b2 = fmaf(x2.x, hb.x, b2); b2 = fmaf(x2.y, hb.y, b2);
        b2 = fmaf(x2.z, hb.z, b2); b2 = fmaf(x2.w, hb.w, b2);
    }
    float bl0 = blin[js * 3 + 0], bl1 = blin[js * 3 + 1], bl2 = blin[js * 3 + 2];
    a0 += bl0; a1 += bl1; a2 += bl2;
    b0 += bl0; b1 += bl1; b2 += bl2;

    float m = fmaxf(a0, fmaxf(a1, a2));
#pragma unroll
    for (int off = 8; off; off >>= 1) m = fmaxf(m, __shfl_xor_sync(0xffffffffu, m, off, 16));
    float e0 = __expf(a0 - m), e1 = __expf(a1 - m), e2 = __expf(a2 - m);
    float s = e0 + e1 + e2;
#pragma unroll
    for (int off = 8; off; off >>= 1) s += __shfl_xor_sync(0xffffffffu, s, off, 16);
    float inv = 1.f / s;
    size_t pa = (n0 + pr * 2) * NT + js * 3;
    g_probs[pa + 0] = e0 * inv;
    g_probs[pa + 1] = e1 * inv;
    g_probs[pa + 2] = e2 * inv;

    m = fmaxf(b0, fmaxf(b1, b2));
#pragma unroll
    for (int off = 8; off; off >>= 1) m = fmaxf(m, __shfl_xor_sync(0xffffffffu, m, off, 16));
    e0 = __expf(b0 - m); e1 = __expf(b1 - m); e2 = __expf(b2 - m);
    s = e0 + e1 + e2;
#pragma unroll
    for (int off = 8; off; off >>= 1) s += __shfl_xor_sync(0xffffffffu, s, off, 16);
    inv = 1.f / s;
    size_t pb = (n0 + pr * 2 + 1) * NT + js * 3;
    g_probs[pb + 0] = e0 * inv;
    g_probs[pb + 1] = e1 * inv;
    g_probs[pb + 2] = e2 * inv;
}
#define LOGITS_SMEM ((24768 + 16384) * 4)

// =====================================================================
// K4: CRF with factored logsumexp (R13 — measured good)
// =====================================================================
__global__ void __launch_bounds__(64) crf_kernel(
    const int* __restrict__ labels, const int* __restrict__ seql,
    const float* __restrict__ trans, const float* __restrict__ st,
    const float* __restrict__ et)
{
    __shared__ float tr[NT * NT];
    __shared__ float etr[NT * NT];
    __shared__ float alpha[2][NT];
    __shared__ float ebuf[NT];
    __shared__ float red[64];
    int b = blockIdx.x, tid = threadIdx.x;

    for (int i = tid; i < NT * NT; i += 64) {
        float v = trans[i];
        tr[i] = v;
        etr[i] = __expf(v);
    }
    int L = seql[b];
    if (tid < NT) alpha[0][tid] = st[tid] + g_probs[(size_t)b * NS * NT + tid];
    __syncthreads();

    int p = 0;
    float mkeep = 0.f;
    for (int t = 1; t < NS; ++t) {
        if (tid < NT) {
            float m0 = alpha[p][0], m1 = alpha[p][1], m2 = alpha[p][2], m3 = alpha[p][3];
#pragma unroll
            for (int i = 4; i < NT; i += 4) {
                m0 = fmaxf(m0, alpha[p][i + 0]); m1 = fmaxf(m1, alpha[p][i + 1]);
                m2 = fmaxf(m2, alpha[p][i + 2]); m3 = fmaxf(m3, alpha[p][i + 3]);
            }
            mkeep = fmaxf(fmaxf(m0, m1), fmaxf(m2, m3));
            ebuf[tid] = __expf(alpha[p][tid] - mkeep);
        }
        __syncthreads();
        if (tid < NT) {
            float s0 = 0.f, s1 = 0.f, s2 = 0.f, s3 = 0.f;
#pragma unroll
            for (int i = 0; i < NT; i += 4) {
                s0 = fmaf(ebuf[i + 0], etr[(i + 0) * NT + tid], s0);
                s1 = fmaf(ebuf[i + 1], etr[(i + 1) * NT + tid], s1);
                s2 = fmaf(ebuf[i + 2], etr[(i + 2) * NT + tid], s2);
                s3 = fmaf(ebuf[i + 3], etr[(i + 3) * NT + tid], s3);
            }
            float em = g_probs[((size_t)b * NS + t) * NT + tid];
            float na = mkeep + __logf((s0 + s1) + (s2 + s3)) + em;
            alpha[1 - p][tid] = (t < L) ? na : alpha[p][tid];
        }
        p = 1 - p;
        __syncthreads();
    }

    float loc = 0.f;
    const int* lb = labels + b * NS;
    for (int t = tid; t < NS; t += 64) {
        int tg = lb[t];
        if (t < L) {
            loc += g_probs[((size_t)b * NS + t) * NT + tg];
            if (t >= 1) loc += tr[lb[t - 1] * NT + tg];
        }
    }
    red[tid] = loc;
    __syncthreads();
    if (tid == 0) {
        float score = 0.f;
        for (int i = 0; i < 64; ++i) score += red[i];
        score += st[lb[0]] + et[lb[L - 1]];
        float m = -1e30f;
        for (int j = 0; j < NT; ++j) m = fmaxf(m, alpha[p][j] + et[j]);
        float s = 0.f;
        for (int j = 0; j < NT; ++j) s += __expf(alpha[p][j] + et[j] - m);
        float logz = m + __logf(s);
        g_res[b] = score - logz;
    }
}

__global__ void final_kernel(float* __restrict__ out) {
    if (threadIdx.x == 0) {
        float s = 0.f;
        for (int b = 0; b < NB; ++b) s += g_res[b];
        out[0] = -s;
    }
}

extern "C" void kernel_launch(void* const* d_in, const int* in_sizes, int n_in,
                              void* d_out, int out_size)
{
    (void)in_sizes; (void)n_in; (void)out_size;
    const int*   tok    = (const int*)d_in[0];
    const int*   seql   = (const int*)d_in[1];
    const int*   labels = (const int*)d_in[2];
    const float* emb    = (const float*)d_in[3];
    const float* wihf   = (const float*)d_in[4];
    const float* whhf   = (const float*)d_in[5];
    const float* bihf   = (const float*)d_in[6];
    const float* bhhf   = (const float*)d_in[7];
    const float* wihb   = (const float*)d_in[8];
    const float* whhb   = (const float*)d_in[9];
    const float* bihb   = (const float*)d_in[10];
    const float* bhhb   = (const float*)d_in[11];
    const float* wlin   = (const float*)d_in[12];
    const float* blin   = (const float*)d_in[13];
    const float* trans  = (const float*)d_in[14];
    const float* st     = (const float*)d_in[15];
    const float* et     = (const float*)d_in[16];
    float* out = (float*)d_out;

    cudaFuncSetAttribute(input_gemm_kernel, cudaFuncAttributeMaxDynamicSharedMemorySize, GEMM_SMEM);
    cudaFuncSetAttribute(lstm_kernel,   cudaFuncAttributeMaxDynamicSharedMemorySize, 172032);
    cudaFuncSetAttribute(logits_kernel, cudaFuncAttributeMaxDynamicSharedMemorySize, LOGITS_SMEM);

    dim3 g1(512, 32);
    input_gemm_kernel<<<g1, 256, GEMM_SMEM>>>(tok, emb, wihf, wihb, bihf, bhhf, bihb, bhhb);
    init_bar_kernel<<<1, 32>>>();
    lstm_kernel<<<128, 256, 172032>>>(whhf, whhb);
    logits_kernel<<<1024, 256, LOGITS_SMEM>>>(wlin, blin);
    crf_kernel<<<64, 64>>>(labels, seql, trans, st, et);
    final_kernel<<<1, 32>>>(out);
}

// round 15
// speedup vs baseline: 1.1009x; 1.1009x over previous
#include <cuda_runtime.h>
#include <cuda_bf16.h>
#include <cstdint>

#define NB   64
#define NS   512
#define NE   300
#define NH   256
#define NG   1024
#define NT   48
#define NH2  512
#define NTOK (NB*NS)

__device__ float g_z[(size_t)2 * NTOK * NG];
__device__ float g_hout[(size_t)NTOK * NH2];
__device__ float g_probs[(size_t)NTOK * NT];
__device__ unsigned short g_hcurb[2 * 2 * NB * NH];     // bf16 h exchange
__device__ unsigned int   g_whh2[2 * 128 * 1024];       // bf16x2-packed W_hh
__device__ int   g_bar[16];
__device__ float g_res[NB];

__device__ __forceinline__ float fast_sig(float x) { return 1.f / (1.f + __expf(-x)); }
__device__ __forceinline__ float fast_tanh(float x) { return 2.f / (1.f + __expf(-2.f * x)) - 1.f; }

__global__ void init_bar_kernel() {
    if (threadIdx.x < 16) g_bar[threadIdx.x] = 0;
}

// one-time W_hh fp32 -> bf16x2 pack: g_whh2[dir][k2*1024 + grow]
__global__ void __launch_bounds__(256) conv_whh_kernel(
    const float* __restrict__ whhf, const float* __restrict__ whhb)
{
    int idx = blockIdx.x * 256 + threadIdx.x;
    if (idx >= 2 * 131072) return;
    int dir = idx >> 17;
    int rem = idx & 131071;
    int k2 = rem >> 10;
    int grow = rem & 1023;
    const float* W = dir ? whhb : whhf;
    unsigned short lo = __bfloat16_as_ushort(__float2bfloat16(W[grow * NH + 2 * k2]));
    unsigned short hi = __bfloat16_as_ushort(__float2bfloat16(W[grow * NH + 2 * k2 + 1]));
    g_whh2[idx] = (unsigned int)lo | ((unsigned int)hi << 16);
}

// =====================================================================
// K1: embedding gather + input projection GEMM (R11/R13 — measured best)
// =====================================================================
__global__ void __launch_bounds__(256) input_gemm_kernel(
    const int* __restrict__ tok, const float* __restrict__ emb,
    const float* __restrict__ wf, const float* __restrict__ wb,
    const float* __restrict__ bif, const float* __restrict__ bhf,
    const float* __restrict__ bib, const float* __restrict__ bhb)
{
    __shared__ float As[60 * 68];
    __shared__ float Bs[60 * 68];
    __shared__ int   ids[64];

    int tid = threadIdx.x;
    int tm = blockIdx.x;
    int tn = blockIdx.y;
    int dir = tn >> 4;
    int rbase = (tn & 15) << 6;
    const float* __restrict__ W = dir ? wb : wf;

    if (tid < 64) ids[tid] = tok[tm * 64 + tid];

    float acc[4][4] = {{0.f}};
    int tx = tid & 15, ty = tid >> 4;
    int fi = tid & 63;
    int fg0 = tid >> 6;

    for (int kc = 0; kc < 5; ++kc) {
        int k0 = kc * 60;
        __syncthreads();
#pragma unroll
        for (int l = 0; l < 4; ++l) {
            int g = fg0 + l * 4;
            if (g < 15) {
                int kk = g * 4;
                float4 av = *(const float4*)&emb[(size_t)ids[fi] * NE + k0 + kk];
                As[(kk + 0) * 68 + fi] = av.x;
                As[(kk + 1) * 68 + fi] = av.y;
                As[(kk + 2) * 68 + fi] = av.z;
                As[(kk + 3) * 68 + fi] = av.w;
                float4 wv = *(const float4*)&W[(size_t)(rbase + fi) * NE + k0 + kk];
                Bs[(kk + 0) * 68 + fi] = wv.x;
                Bs[(kk + 1) * 68 + fi] = wv.y;
                Bs[(kk + 2) * 68 + fi] = wv.z;
                Bs[(kk + 3) * 68 + fi] = wv.w;
            }
        }
        __syncthreads();
#pragma unroll 4
        for (int k = 0; k < 60; ++k) {
            float4 a4 = *(const float4*)(As + k * 68 + ty * 4);
            float4 b4 = *(const float4*)(Bs + k * 68 + tx * 4);
            float av[4] = {a4.x, a4.y, a4.z, a4.w};
            float bv[4] = {b4.x, b4.y, b4.z, b4.w};
#pragma unroll
            for (int ii = 0; ii < 4; ++ii)
#pragma unroll
                for (int jj = 0; jj < 4; ++jj)
                    acc[ii][jj] = fmaf(av[ii], bv[jj], acc[ii][jj]);
        }
    }

    const float* bi = dir ? bib : bif;
    const float* bh = dir ? bhb : bhf;
    int gcol = rbase + tx * 4;
    float bx = bi[gcol + 0] + bh[gcol + 0];
    float by = bi[gcol + 1] + bh[gcol + 1];
    float bz = bi[gcol + 2] + bh[gcol + 2];
    float bw = bi[gcol + 3] + bh[gcol + 3];

#pragma unroll
    for (int ii = 0; ii < 4; ++ii) {
        int n = tm * 64 + ty * 4 + ii;
        float4 v;
        v.x = acc[ii][0] + bx; v.y = acc[ii][1] + by;
        v.z = acc[ii][2] + bz; v.w = acc[ii][3] + bw;
        *(float4*)&g_z[((size_t)dir * NTOK + n) * NG + gcol] = v;
    }
}

// =====================================================================
// K2: persistent BiLSTM recurrence, bf16x2 HFMA2 inner loop (2x MAC
// rate). W slice packed bf16x2 in smem (64KB); h exchanged as bf16;
// chain combine + activation + state all fp32.
// =====================================================================
__global__ void __launch_bounds__(256) lstm_kernel()
{
    extern __shared__ float sm[];
    unsigned int* Wsb = (unsigned int*)sm;            // 16384 u32 (64KB)
    unsigned int* hs2 = (unsigned int*)(sm + 16384);  // 1024 u32 (4KB)
    float* red = sm + 17408;                          // 8192 floats (32KB)

    int bid = blockIdx.x;
    int dir = bid >> 6;
    int bg  = (bid >> 3) & 7;
    int sl  = bid & 7;
    int us  = sl << 5;
    int tid = threadIdx.x;
    int w   = tid >> 5;
    int lane = tid & 31;

    for (int idx = tid; idx < 16384; idx += 256) {
        int r = idx & 127, k2 = idx >> 7;
        Wsb[idx] = g_whh2[dir * 131072 + k2 * 1024 + (r & 3) * NH + us + (r >> 2)];
    }
    for (int i = tid; i < 1024; i += 256) hs2[i] = 0u;
    __syncthreads();

    int b = bg * 8 + w;
    int u = us + lane;
    int bar = dir * 8 + bg;
    int k20 = w * 16;                 // this warp's k2 range [16w, 16w+16)
    const uint4* wp = ((const uint4*)Wsb) + lane;
    int* barp = &g_bar[bar];
    float c = 0.f;

    for (int t = 0; t < NS; ++t) {
        int to = dir ? (NS - 1 - t) : t;

        __nv_bfloat162 acc0[8], acc1[8], acc2[8], acc3[8];
        __nv_bfloat162 z2 = __float2bfloat162_rn(0.f);
#pragma unroll
        for (int bb = 0; bb < 8; ++bb) { acc0[bb] = z2; acc1[bb] = z2; acc2[bb] = z2; acc3[bb] = z2; }

#pragma unroll 4
        for (int kk = 0; kk < 16; ++kk) {
            int k2 = k20 + kk;
            uint4 wv = wp[k2 * 32];
            __nv_bfloat162 w0 = *(__nv_bfloat162*)&wv.x;
            __nv_bfloat162 w1 = *(__nv_bfloat162*)&wv.y;
            __nv_bfloat162 w2 = *(__nv_bfloat162*)&wv.z;
            __nv_bfloat162 w3 = *(__nv_bfloat162*)&wv.w;
#pragma unroll
            for (int bb = 0; bb < 8; ++bb) {
                unsigned int hraw = hs2[bb * 128 + k2];
                __nv_bfloat162 h2 = *(__nv_bfloat162*)&hraw;
                acc0[bb] = __hfma2(w0, h2, acc0[bb]);
                acc1[bb] = __hfma2(w1, h2, acc1[bb]);
                acc2[bb] = __hfma2(w2, h2, acc2[bb]);
                acc3[bb] = __hfma2(w3, h2, acc3[bb]);
            }
        }
#pragma unroll
        for (int bb = 0; bb < 8; ++bb) {
            float2 e0 = __bfloat1622float2(acc0[bb]);
            float2 e1 = __bfloat1622float2(acc1[bb]);
            float2 e2 = __bfloat1622float2(acc2[bb]);
            float2 e3 = __bfloat1622float2(acc3[bb]);
            float4 v;
            v.x = e0.x + e0.y; v.y = e1.x + e1.y;
            v.z = e2.x + e2.y; v.w = e3.x + e3.y;
            *(float4*)&red[((w * 8 + bb) * 32 + lane) * 4] = v;
        }

        size_t zb = ((size_t)dir * NTOK + (size_t)b * NS + to) * NG + u;
        float zi = g_z[zb], zf = g_z[zb + 256], zg = g_z[zb + 512], zo = g_z[zb + 768];
        __syncthreads();

        float a0 = zi, a1 = zf, a2 = zg, a3 = zo;
#pragma unroll
        for (int ww = 0; ww < 8; ++ww) {
            float4 p = *(const float4*)&red[((ww * 8 + w) * 32 + lane) * 4];
            a0 += p.x; a1 += p.y; a2 += p.z; a3 += p.w;
        }

        float ig = fast_sig(a0), fg = fast_sig(a1);
        float gg = fast_tanh(a2), og = fast_sig(a3);
        c = fg * c + ig * gg;
        float hn = og * fast_tanh(c);

        int wbuf = t & 1;
        g_hcurb[((wbuf * 2 + dir) * NB + b) * NH + u] =
            __bfloat16_as_ushort(__float2bfloat16(hn));

        __syncthreads();
        if (tid == 0) {
            asm volatile("red.release.gpu.global.add.s32 [%0], 1;"
                         :: "l"(barp) : "memory");
        }
        g_hout[((size_t)b * NS + to) * NH2 + dir * NH + u] = hn;

        if (tid == 0) {
            int tgt = 8 * (t + 1);
            int v;
            do {
                asm volatile("ld.acquire.gpu.global.s32 %0, [%1];"
                             : "=r"(v) : "l"(barp) : "memory");
            } while (v < tgt);
        }
        __syncthreads();

        if (t < NS - 1) {
            const uint4* src = (const uint4*)&g_hcurb[((size_t)(wbuf * 2 + dir) * NB + bg * 8) * NH];
            uint4* dst = (uint4*)hs2;
            if (tid < 256) dst[tid] = __ldcg(src + tid);
            __syncthreads();
        }
    }
}
#define LSTM_SMEM ((16384 + 1024 + 8192) * 4)   // 102400

// =====================================================================
// K3: logits + softmax (R12 — measured good)
// =====================================================================
__global__ void __launch_bounds__(256) logits_kernel(
    const float* __restrict__ wlin, const float* __restrict__ blin)
{
    extern __shared__ float sm[];
    float* ws  = sm;
    float* hsm = sm + 24768;
    int tid = threadIdx.x;
    size_t n0 = (size_t)blockIdx.x * 32;

    for (int i4 = tid; i4 < (NT * NH2) / 4; i4 += 256) {
        int i = i4 * 4;
        float4 v = *(const float4*)&wlin[i];
        *(float4*)&ws[(i >> 9) * 516 + (i & 511)] = v;
    }
    for (int i4 = tid; i4 < (32 * NH2) / 4; i4 += 256) {
        float4 v = *(const float4*)&g_hout[n0 * NH2 + (size_t)i4 * 4];
        *(float4*)&hsm[i4 * 4] = v;
    }
    __syncthreads();

    int pr = tid >> 4, js = tid & 15;
    const float4* h0 = (const float4*)(hsm + (pr * 2 + 0) * NH2);
    const float4* h1 = (const float4*)(hsm + (pr * 2 + 1) * NH2);
    const float4* w0 = (const float4*)(ws + (js * 3 + 0) * 516);
    const float4* w1 = (const float4*)(ws + (js * 3 + 1) * 516);
    const float4* w2 = (const float4*)(ws + (js * 3 + 2) * 516);
    float a0 = 0.f, a1 = 0.f, a2 = 0.f;
    float b0 = 0.f, b1 = 0.f, b2 = 0.f;
#pragma unroll 4
    for (int kk = 0; kk < 128; ++kk) {
        float4 ha = h0[kk];
        float4 hb = h1[kk];
        float4 x0 = w0[kk];
        float4 x1 = w1[kk];
        float4 x2 = w2[kk];
        a0 = fmaf(x0.x, ha.x, a0); a0 = fmaf(x0.y, ha.y, a0);
        a0 = fmaf(x0.z, ha.z, a0); a0 = fmaf(x0.w, ha.w, a0);
        a1 = fmaf(x1.x, ha.x, a1); a1 = fmaf(x1.y, ha.y, a1);
        a1 = fmaf(x1.z, ha.z, a1); a1 = fmaf(x1.w, ha.w, a1);
        a2 = fmaf(x2.x, ha.x, a2); a2 = fmaf(x2.y, ha.y, a2);
        a2 = fmaf(x2.z, ha.z, a2); a2 = fmaf(x2.w, ha.w, a2);
        b0 = fmaf(x0.x, hb.x, b0); b0 = fmaf(x0.y, hb.y, b0);
        b0 = fmaf(x0.z, hb.z, b0); b0 = fmaf(x0.w, hb.w, b0);
        b1 = fmaf(x1.x, hb.x, b1); b1 = fmaf(x1.y, hb.y, b1);
        b1 = fmaf(x1.z, hb.z, b1); b1 = fmaf(x1.w, hb.w, b1);
        b2 = fmaf(x2.x, hb.x, b2); b2 = fmaf(x2.y, hb.y, b2);
        b2 = fmaf(x2.z, hb.z, b2); b2 = fmaf(x2.w, hb.w, b2);
    }
    float bl0 = blin[js * 3 + 0], bl1 = blin[js * 3 + 1], bl2 = blin[js * 3 + 2];
    a0 += bl0; a1 += bl1; a2 += bl2;
    b0 += bl0; b1 += bl1; b2 += bl2;

    float m = fmaxf(a0, fmaxf(a1, a2));
#pragma unroll
    for (int off = 8; off; off >>= 1) m = fmaxf(m, __shfl_xor_sync(0xffffffffu, m, off, 16));
    float e0 = __expf(a0 - m), e1 = __expf(a1 - m), e2 = __expf(a2 - m);
    float s = e0 + e1 + e2;
#pragma unroll
    for (int off = 8; off; off >>= 1) s += __shfl_xor_sync(0xffffffffu, s, off, 16);
    float inv = 1.f / s;
    size_t pa = (n0 + pr * 2) * NT + js * 3;
    g_probs[pa + 0] = e0 * inv;
    g_probs[pa + 1] = e1 * inv;
    g_probs[pa + 2] = e2 * inv;

    m = fmaxf(b0, fmaxf(b1, b2));
#pragma unroll
    for (int off = 8; off; off >>= 1) m = fmaxf(m, __shfl_xor_sync(0xffffffffu, m, off, 16));
    e0 = __expf(b0 - m); e1 = __expf(b1 - m); e2 = __expf(b2 - m);
    s = e0 + e1 + e2;
#pragma unroll
    for (int off = 8; off; off >>= 1) s += __shfl_xor_sync(0xffffffffu, s, off, 16);
    inv = 1.f / s;
    size_t pb = (n0 + pr * 2 + 1) * NT + js * 3;
    g_probs[pb + 0] = e0 * inv;
    g_probs[pb + 1] = e1 * inv;
    g_probs[pb + 2] = e2 * inv;
}
#define LOGITS_SMEM ((24768 + 16384) * 4)

// =====================================================================
// K4: CRF with factored logsumexp (R13 — measured good)
// =====================================================================
__global__ void __launch_bounds__(64) crf_kernel(
    const int* __restrict__ labels, const int* __restrict__ seql,
    const float* __restrict__ trans, const float* __restrict__ st,
    const float* __restrict__ et)
{
    __shared__ float tr[NT * NT];
    __shared__ float etr[NT * NT];
    __shared__ float alpha[2][NT];
    __shared__ float ebuf[NT];
    __shared__ float red[64];
    int b = blockIdx.x, tid = threadIdx.x;

    for (int i = tid; i < NT * NT; i += 64) {
        float v = trans[i];
        tr[i] = v;
        etr[i] = __expf(v);
    }
    int L = seql[b];
    if (tid < NT) alpha[0][tid] = st[tid] + g_probs[(size_t)b * NS * NT + tid];
    __syncthreads();

    int p = 0;
    float mkeep = 0.f;
    for (int t = 1; t < NS; ++t) {
        if (tid < NT) {
            float m0 = alpha[p][0], m1 = alpha[p][1], m2 = alpha[p][2], m3 = alpha[p][3];
#pragma unroll
            for (int i = 4; i < NT; i += 4) {
                m0 = fmaxf(m0, alpha[p][i + 0]); m1 = fmaxf(m1, alpha[p][i + 1]);
                m2 = fmaxf(m2, alpha[p][i + 2]); m3 = fmaxf(m3, alpha[p][i + 3]);
            }
            mkeep = fmaxf(fmaxf(m0, m1), fmaxf(m2, m3));
            ebuf[tid] = __expf(alpha[p][tid] - mkeep);
        }
        __syncthreads();
        if (tid < NT) {
            float s0 = 0.f, s1 = 0.f, s2 = 0.f, s3 = 0.f;
#pragma unroll
            for (int i = 0; i < NT; i += 4) {
                s0 = fmaf(ebuf[i + 0], etr[(i + 0) * NT + tid], s0);
                s1 = fmaf(ebuf[i + 1], etr[(i + 1) * NT + tid], s1);
                s2 = fmaf(ebuf[i + 2], etr[(i + 2) * NT + tid], s2);
                s3 = fmaf(ebuf[i + 3], etr[(i + 3) * NT + tid], s3);
            }
            float em = g_probs[((size_t)b * NS + t) * NT + tid];
            float na = mkeep + __logf((s0 + s1) + (s2 + s3)) + em;
            alpha[1 - p][tid] = (t < L) ? na : alpha[p][tid];
        }
        p = 1 - p;
        __syncthreads();
    }

    float loc = 0.f;
    const int* lb = labels + b * NS;
    for (int t = tid; t < NS; t += 64) {
        int tg = lb[t];
        if (t < L) {
            loc += g_probs[((size_t)b * NS + t) * NT + tg];
            if (t >= 1) loc += tr[lb[t - 1] * NT + tg];
        }
    }
    red[tid] = loc;
    __syncthreads();
    if (tid == 0) {
        float score = 0.f;
        for (int i = 0; i < 64; ++i) score += red[i];
        score += st[lb[0]] + et[lb[L - 1]];
        float m = -1e30f;
        for (int j = 0; j < NT; ++j) m = fmaxf(m, alpha[p][j] + et[j]);
        float s = 0.f;
        for (int j = 0; j < NT; ++j) s += __expf(alpha[p][j] + et[j] - m);
        float logz = m + __logf(s);
        g_res[b] = score - logz;
    }
}

__global__ void final_kernel(float* __restrict__ out) {
    if (threadIdx.x == 0) {
        float s = 0.f;
        for (int b = 0; b < NB; ++b) s += g_res[b];
        out[0] = -s;
    }
}

extern "C" void kernel_launch(void* const* d_in, const int* in_sizes, int n_in,
                              void* d_out, int out_size)
{
    (void)in_sizes; (void)n_in; (void)out_size;
    const int*   tok    = (const int*)d_in[0];
    const int*   seql   = (const int*)d_in[1];
    const int*   labels = (const int*)d_in[2];
    const float* emb    = (const float*)d_in[3];
    const float* wihf   = (const float*)d_in[4];
    const float* whhf   = (const float*)d_in[5];
    const float* bihf   = (const float*)d_in[6];
    const float* bhhf   = (const float*)d_in[7];
    const float* wihb   = (const float*)d_in[8];
    const float* whhb   = (const float*)d_in[9];
    const float* bihb   = (const float*)d_in[10];
    const float* bhhb   = (const float*)d_in[11];
    const float* wlin   = (const float*)d_in[12];
    const float* blin   = (const float*)d_in[13];
    const float* trans  = (const float*)d_in[14];
    const float* st     = (const float*)d_in[15];
    const float* et     = (const float*)d_in[16];
    float* out = (float*)d_out;

    cudaFuncSetAttribute(lstm_kernel,   cudaFuncAttributeMaxDynamicSharedMemorySize, LSTM_SMEM);
    cudaFuncSetAttribute(logits_kernel, cudaFuncAttributeMaxDynamicSharedMemorySize, LOGITS_SMEM);

    conv_whh_kernel<<<(2 * 131072 + 255) / 256, 256>>>(whhf, whhb);
    dim3 g1(512, 32);
    input_gemm_kernel<<<g1, 256>>>(tok, emb, wihf, wihb, bihf, bhhf, bihb, bhhb);
    init_bar_kernel<<<1, 32>>>();
    lstm_kernel<<<128, 256, LSTM_SMEM>>>();
    logits_kernel<<<1024, 256, LOGITS_SMEM>>>(wlin, blin);
    crf_kernel<<<64, 64>>>(labels, seql, trans, st, et);
    final_kernel<<<1, 32>>>(out);
}

// round 16
// speedup vs baseline: 1.2185x; 1.1069x over previous
#include <cuda_runtime.h>
#include <cuda_bf16.h>
#include <cstdint>

#define NB   64
#define NS   512
#define NE   300
#define NH   256
#define NG   1024
#define NT   48
#define NH2  512
#define NTOK (NB*NS)

__device__ float g_z[(size_t)2 * NTOK * NG];
__device__ float g_hout[(size_t)NTOK * NH2];
__device__ float g_probs[(size_t)NTOK * NT];
__device__ unsigned short g_hcurb[2 * 2 * NB * NH];     // bf16 h exchange
__device__ unsigned int   g_whh2[2 * 128 * 1024];       // bf16x2-packed W_hh
__device__ int   g_bar[16];
__device__ float g_res[NB];

__device__ __forceinline__ float fast_sig(float x) { return 1.f / (1.f + __expf(-x)); }
__device__ __forceinline__ float fast_tanh(float x) { return 2.f / (1.f + __expf(-2.f * x)) - 1.f; }

__global__ void init_bar_kernel() {
    if (threadIdx.x < 16) g_bar[threadIdx.x] = 0;
}

// one-time W_hh fp32 -> bf16x2 pack: g_whh2[dir][k2*1024 + grow]
__global__ void __launch_bounds__(256) conv_whh_kernel(
    const float* __restrict__ whhf, const float* __restrict__ whhb)
{
    int idx = blockIdx.x * 256 + threadIdx.x;
    if (idx >= 2 * 131072) return;
    int dir = idx >> 17;
    int rem = idx & 131071;
    int k2 = rem >> 10;
    int grow = rem & 1023;
    const float* W = dir ? whhb : whhf;
    unsigned short lo = __bfloat16_as_ushort(__float2bfloat16(W[grow * NH + 2 * k2]));
    unsigned short hi = __bfloat16_as_ushort(__float2bfloat16(W[grow * NH + 2 * k2 + 1]));
    g_whh2[idx] = (unsigned int)lo | ((unsigned int)hi << 16);
}

// =====================================================================
// K1: embedding gather + input projection GEMM, bf16x2 HFMA2.
// 64x64 tile, 4x4 microtile; per k-pair: 2 LDS.128 + 16 HFMA2 (2 k).
// bf16x2 accumulator chains of 30 k-pairs, fp32 combine per chunk.
// =====================================================================
__global__ void __launch_bounds__(256) input_gemm_kernel(
    const int* __restrict__ tok, const float* __restrict__ emb,
    const float* __restrict__ wf, const float* __restrict__ wb,
    const float* __restrict__ bif, const float* __restrict__ bhf,
    const float* __restrict__ bib, const float* __restrict__ bhb)
{
    __shared__ unsigned int As2[30 * 64];   // [k2][token] bf16x2
    __shared__ unsigned int Bs2[30 * 64];   // [k2][gate]  bf16x2
    __shared__ int ids[64];

    int tid = threadIdx.x;
    int tm = blockIdx.x;
    int tn = blockIdx.y;
    int dir = tn >> 4;
    int rbase = (tn & 15) << 6;
    const float* __restrict__ W = dir ? wb : wf;

    if (tid < 64) ids[tid] = tok[tm * 64 + tid];

    float accf[4][4] = {{0.f}};
    int tx = tid & 15, ty = tid >> 4;
    int fi = tid & 63;
    int fg0 = tid >> 6;

    for (int kc = 0; kc < 5; ++kc) {
        int k0 = kc * 60;
        __syncthreads();
#pragma unroll
        for (int l = 0; l < 4; ++l) {
            int g = fg0 + l * 4;
            if (g < 15) {
                float4 av = *(const float4*)&emb[(size_t)ids[fi] * NE + k0 + g * 4];
                __nv_bfloat162 a0 = __float22bfloat162_rn(make_float2(av.x, av.y));
                __nv_bfloat162 a1 = __float22bfloat162_rn(make_float2(av.z, av.w));
                As2[(g * 2 + 0) * 64 + fi] = *(unsigned int*)&a0;
                As2[(g * 2 + 1) * 64 + fi] = *(unsigned int*)&a1;
                float4 wv = *(const float4*)&W[(size_t)(rbase + fi) * NE + k0 + g * 4];
                __nv_bfloat162 b0 = __float22bfloat162_rn(make_float2(wv.x, wv.y));
                __nv_bfloat162 b1 = __float22bfloat162_rn(make_float2(wv.z, wv.w));
                Bs2[(g * 2 + 0) * 64 + fi] = *(unsigned int*)&b0;
                Bs2[(g * 2 + 1) * 64 + fi] = *(unsigned int*)&b1;
            }
        }
        __syncthreads();

        __nv_bfloat162 acc2[4][4];
        __nv_bfloat162 zz = __float2bfloat162_rn(0.f);
#pragma unroll
        for (int ii = 0; ii < 4; ++ii)
#pragma unroll
            for (int jj = 0; jj < 4; ++jj) acc2[ii][jj] = zz;

#pragma unroll 6
        for (int k2 = 0; k2 < 30; ++k2) {
            uint4 ar = *(const uint4*)(As2 + k2 * 64 + ty * 4);
            uint4 br = *(const uint4*)(Bs2 + k2 * 64 + tx * 4);
            __nv_bfloat162 a[4] = {*(__nv_bfloat162*)&ar.x, *(__nv_bfloat162*)&ar.y,
                                   *(__nv_bfloat162*)&ar.z, *(__nv_bfloat162*)&ar.w};
            __nv_bfloat162 b[4] = {*(__nv_bfloat162*)&br.x, *(__nv_bfloat162*)&br.y,
                                   *(__nv_bfloat162*)&br.z, *(__nv_bfloat162*)&br.w};
#pragma unroll
            for (int ii = 0; ii < 4; ++ii)
#pragma unroll
                for (int jj = 0; jj < 4; ++jj)
                    acc2[ii][jj] = __hfma2(a[ii], b[jj], acc2[ii][jj]);
        }
#pragma unroll
        for (int ii = 0; ii < 4; ++ii)
#pragma unroll
            for (int jj = 0; jj < 4; ++jj) {
                float2 e = __bfloat1622float2(acc2[ii][jj]);
                accf[ii][jj] += e.x + e.y;
            }
    }

    const float* bi = dir ? bib : bif;
    const float* bh = dir ? bhb : bhf;
    int gcol = rbase + tx * 4;
    float bx = bi[gcol + 0] + bh[gcol + 0];
    float by = bi[gcol + 1] + bh[gcol + 1];
    float bz = bi[gcol + 2] + bh[gcol + 2];
    float bw = bi[gcol + 3] + bh[gcol + 3];

#pragma unroll
    for (int ii = 0; ii < 4; ++ii) {
        int n = tm * 64 + ty * 4 + ii;
        float4 v;
        v.x = accf[ii][0] + bx; v.y = accf[ii][1] + by;
        v.z = accf[ii][2] + bz; v.w = accf[ii][3] + bw;
        *(float4*)&g_z[((size_t)dir * NTOK + n) * NG + gcol] = v;
    }
}

// =====================================================================
// K2: persistent BiLSTM recurrence, bf16x2 HFMA2 (R15 — measured good)
// =====================================================================
__global__ void __launch_bounds__(256) lstm_kernel()
{
    extern __shared__ float sm[];
    unsigned int* Wsb = (unsigned int*)sm;            // 16384 u32 (64KB)
    unsigned int* hs2 = (unsigned int*)(sm + 16384);  // 1024 u32 (4KB)
    float* red = sm + 17408;                          // 8192 floats (32KB)

    int bid = blockIdx.x;
    int dir = bid >> 6;
    int bg  = (bid >> 3) & 7;
    int sl  = bid & 7;
    int us  = sl << 5;
    int tid = threadIdx.x;
    int w   = tid >> 5;
    int lane = tid & 31;

    for (int idx = tid; idx < 16384; idx += 256) {
        int r = idx & 127, k2 = idx >> 7;
        Wsb[idx] = g_whh2[dir * 131072 + k2 * 1024 + (r & 3) * NH + us + (r >> 2)];
    }
    for (int i = tid; i < 1024; i += 256) hs2[i] = 0u;
    __syncthreads();

    int b = bg * 8 + w;
    int u = us + lane;
    int bar = dir * 8 + bg;
    int k20 = w * 16;
    const uint4* wp = ((const uint4*)Wsb) + lane;
    int* barp = &g_bar[bar];
    float c = 0.f;

    for (int t = 0; t < NS; ++t) {
        int to = dir ? (NS - 1 - t) : t;

        __nv_bfloat162 acc0[8], acc1[8], acc2[8], acc3[8];
        __nv_bfloat162 z2 = __float2bfloat162_rn(0.f);
#pragma unroll
        for (int bb = 0; bb < 8; ++bb) { acc0[bb] = z2; acc1[bb] = z2; acc2[bb] = z2; acc3[bb] = z2; }

#pragma unroll 4
        for (int kk = 0; kk < 16; ++kk) {
            int k2 = k20 + kk;
            uint4 wv = wp[k2 * 32];
            __nv_bfloat162 w0 = *(__nv_bfloat162*)&wv.x;
            __nv_bfloat162 w1 = *(__nv_bfloat162*)&wv.y;
            __nv_bfloat162 w2 = *(__nv_bfloat162*)&wv.z;
            __nv_bfloat162 w3 = *(__nv_bfloat162*)&wv.w;
#pragma unroll
            for (int bb = 0; bb < 8; ++bb) {
                unsigned int hraw = hs2[bb * 128 + k2];
                __nv_bfloat162 h2 = *(__nv_bfloat162*)&hraw;
                acc0[bb] = __hfma2(w0, h2, acc0[bb]);
                acc1[bb] = __hfma2(w1, h2, acc1[bb]);
                acc2[bb] = __hfma2(w2, h2, acc2[bb]);
                acc3[bb] = __hfma2(w3, h2, acc3[bb]);
            }
        }
#pragma unroll
        for (int bb = 0; bb < 8; ++bb) {
            float2 e0 = __bfloat1622float2(acc0[bb]);
            float2 e1 = __bfloat1622float2(acc1[bb]);
            float2 e2 = __bfloat1622float2(acc2[bb]);
            float2 e3 = __bfloat1622float2(acc3[bb]);
            float4 v;
            v.x = e0.x + e0.y; v.y = e1.x + e1.y;
            v.z = e2.x + e2.y; v.w = e3.x + e3.y;
            *(float4*)&red[((w * 8 + bb) * 32 + lane) * 4] = v;
        }

        size_t zb = ((size_t)dir * NTOK + (size_t)b * NS + to) * NG + u;
        float zi = g_z[zb], zf = g_z[zb + 256], zg = g_z[zb + 512], zo = g_z[zb + 768];
        __syncthreads();

        float a0 = zi, a1 = zf, a2 = zg, a3 = zo;
#pragma unroll
        for (int ww = 0; ww < 8; ++ww) {
            float4 p = *(const float4*)&red[((ww * 8 + w) * 32 + lane) * 4];
            a0 += p.x; a1 += p.y; a2 += p.z; a3 += p.w;
        }

        float ig = fast_sig(a0), fg = fast_sig(a1);
        float gg = fast_tanh(a2), og = fast_sig(a3);
        c = fg * c + ig * gg;
        float hn = og * fast_tanh(c);

        int wbuf = t & 1;
        g_hcurb[((wbuf * 2 + dir) * NB + b) * NH + u] =
            __bfloat16_as_ushort(__float2bfloat16(hn));

        __syncthreads();
        if (tid == 0) {
            asm volatile("red.release.gpu.global.add.s32 [%0], 1;"
                         :: "l"(barp) : "memory");
        }
        g_hout[((size_t)b * NS + to) * NH2 + dir * NH + u] = hn;

        if (tid == 0) {
            int tgt = 8 * (t + 1);
            int v;
            do {
                asm volatile("ld.acquire.gpu.global.s32 %0, [%1];"
                             : "=r"(v) : "l"(barp) : "memory");
            } while (v < tgt);
        }
        __syncthreads();

        if (t < NS - 1) {
            const uint4* src = (const uint4*)&g_hcurb[((size_t)(wbuf * 2 + dir) * NB + bg * 8) * NH];
            uint4* dst = (uint4*)hs2;
            if (tid < 256) dst[tid] = __ldcg(src + tid);
            __syncthreads();
        }
    }
}
#define LSTM_SMEM ((16384 + 1024 + 8192) * 4)   // 102400

// =====================================================================
// K3: logits + softmax (R12 — measured good)
// =====================================================================
__global__ void __launch_bounds__(256) logits_kernel(
    const float* __restrict__ wlin, const float* __restrict__ blin)
{
    extern __shared__ float sm[];
    float* ws  = sm;
    float* hsm = sm + 24768;
    int tid = threadIdx.x;
    size_t n0 = (size_t)blockIdx.x * 32;

    for (int i4 = tid; i4 < (NT * NH2) / 4; i4 += 256) {
        int i = i4 * 4;
        float4 v = *(const float4*)&wlin[i];
        *(float4*)&ws[(i >> 9) * 516 + (i & 511)] = v;
    }
    for (int i4 = tid; i4 < (32 * NH2) / 4; i4 += 256) {
        float4 v = *(const float4*)&g_hout[n0 * NH2 + (size_t)i4 * 4];
        *(float4*)&hsm[i4 * 4] = v;
    }
    __syncthreads();

    int pr = tid >> 4, js = tid & 15;
    const float4* h0 = (const float4*)(hsm + (pr * 2 + 0) * NH2);
    const float4* h1 = (const float4*)(hsm + (pr * 2 + 1) * NH2);
    const float4* w0 = (const float4*)(ws + (js * 3 + 0) * 516);
    const float4* w1 = (const float4*)(ws + (js * 3 + 1) * 516);
    const float4* w2 = (const float4*)(ws + (js * 3 + 2) * 516);
    float a0 = 0.f, a1 = 0.f, a2 = 0.f;
    float b0 = 0.f, b1 = 0.f, b2 = 0.f;
#pragma unroll 4
    for (int kk = 0; kk < 128; ++kk) {
        float4 ha = h0[kk];
        float4 hb = h1[kk];
        float4 x0 = w0[kk];
        float4 x1 = w1[kk];
        float4 x2 = w2[kk];
        a0 = fmaf(x0.x, ha.x, a0); a0 = fmaf(x0.y, ha.y, a0);
        a0 = fmaf(x0.z, ha.z, a0); a0 = fmaf(x0.w, ha.w, a0);
        a1 = fmaf(x1.x, ha.x, a1); a1 = fmaf(x1.y, ha.y, a1);
        a1 = fmaf(x1.z, ha.z, a1); a1 = fmaf(x1.w, ha.w, a1);
        a2 = fmaf(x2.x, ha.x, a2); a2 = fmaf(x2.y, ha.y, a2);
        a2 = fmaf(x2.z, ha.z, a2); a2 = fmaf(x2.w, ha.w, a2);
        b0 = fmaf(x0.x, hb.x, b0); b0 = fmaf(x0.y, hb.y, b0);
        b0 = fmaf(x0.z, hb.z, b0); b0 = fmaf(x0.w, hb.w, b0);
        b1 = fmaf(x1.x, hb.x, b1); b1 = fmaf(x1.y, hb.y, b1);
        b1 = fmaf(x1.z, hb.z, b1); b1 = fmaf(x1.w, hb.w, b1);
        b2 = fmaf(x2.x, hb.x, b2); b2 = fmaf(x2.y, hb.y, b2);
        b2 = fmaf(x2.z, hb.z, b2); b2 = fmaf(x2.w, hb.w, b2);
    }
    float bl0 = blin[js * 3 + 0], bl1 = blin[js * 3 + 1], bl2 = blin[js * 3 + 2];
    a0 += bl0; a1 += bl1; a2 += bl2;
    b0 += bl0; b1 += bl1; b2 += bl2;

    float m = fmaxf(a0, fmaxf(a1, a2));
#pragma unroll
    for (int off = 8; off; off >>= 1) m = fmaxf(m, __shfl_xor_sync(0xffffffffu, m, off, 16));
    float e0 = __expf(a0 - m), e1 = __expf(a1 - m), e2 = __expf(a2 - m);
    float s = e0 + e1 + e2;
#pragma unroll
    for (int off = 8; off; off >>= 1) s += __shfl_xor_sync(0xffffffffu, s, off, 16);
    float inv = 1.f / s;
    size_t pa = (n0 + pr * 2) * NT + js * 3;
    g_probs[pa + 0] = e0 * inv;
    g_probs[pa + 1] = e1 * inv;
    g_probs[pa + 2] = e2 * inv;

    m = fmaxf(b0, fmaxf(b1, b2));
#pragma unroll
    for (int off = 8; off; off >>= 1) m = fmaxf(m, __shfl_xor_sync(0xffffffffu, m, off, 16));
    e0 = __expf(b0 - m); e1 = __expf(b1 - m); e2 = __expf(b2 - m);
    s = e0 + e1 + e2;
#pragma unroll
    for (int off = 8; off; off >>= 1) s += __shfl_xor_sync(0xffffffffu, s, off, 16);
    inv = 1.f / s;
    size_t pb = (n0 + pr * 2 + 1) * NT + js * 3;
    g_probs[pb + 0] = e0 * inv;
    g_probs[pb + 1] = e1 * inv;
    g_probs[pb + 2] = e2 * inv;
}
#define LOGITS_SMEM ((24768 + 16384) * 4)

// =====================================================================
// K4: CRF with factored logsumexp (R13 — measured good)
// =====================================================================
__global__ void __launch_bounds__(64) crf_kernel(
    const int* __restrict__ labels, const int* __restrict__ seql,
    const float* __restrict__ trans, const float* __restrict__ st,
    const float* __restrict__ et)
{
    __shared__ float tr[NT * NT];
    __shared__ float etr[NT * NT];
    __shared__ float alpha[2][NT];
    __shared__ float ebuf[NT];
    __shared__ float red[64];
    int b = blockIdx.x, tid = threadIdx.x;

    for (int i = tid; i < NT * NT; i += 64) {
        float v = trans[i];
        tr[i] = v;
        etr[i] = __expf(v);
    }
    int L = seql[b];
    if (tid < NT) alpha[0][tid] = st[tid] + g_probs[(size_t)b * NS * NT + tid];
    __syncthreads();

    int p = 0;
    float mkeep = 0.f;
    for (int t = 1; t < NS; ++t) {
        if (tid < NT) {
            float m0 = alpha[p][0], m1 = alpha[p][1], m2 = alpha[p][2], m3 = alpha[p][3];
#pragma unroll
            for (int i = 4; i < NT; i += 4) {
                m0 = fmaxf(m0, alpha[p][i + 0]); m1 = fmaxf(m1, alpha[p][i + 1]);
                m2 = fmaxf(m2, alpha[p][i + 2]); m3 = fmaxf(m3, alpha[p][i + 3]);
            }
            mkeep = fmaxf(fmaxf(m0, m1), fmaxf(m2, m3));
            ebuf[tid] = __expf(alpha[p][tid] - mkeep);
        }
        __syncthreads();
        if (tid < NT) {
            float s0 = 0.f, s1 = 0.f, s2 = 0.f, s3 = 0.f;
#pragma unroll
            for (int i = 0; i < NT; i += 4) {
                s0 = fmaf(ebuf[i + 0], etr[(i + 0) * NT + tid], s0);
                s1 = fmaf(ebuf[i + 1], etr[(i + 1) * NT + tid], s1);
                s2 = fmaf(ebuf[i + 2], etr[(i + 2) * NT + tid], s2);
                s3 = fmaf(ebuf[i + 3], etr[(i + 3) * NT + tid], s3);
            }
            float em = g_probs[((size_t)b * NS + t) * NT + tid];
            float na = mkeep + __logf((s0 + s1) + (s2 + s3)) + em;
            alpha[1 - p][tid] = (t < L) ? na : alpha[p][tid];
        }
        p = 1 - p;
        __syncthreads();
    }

    float loc = 0.f;
    const int* lb = labels + b * NS;
    for (int t = tid; t < NS; t += 64) {
        int tg = lb[t];
        if (t < L) {
            loc += g_probs[((size_t)b * NS + t) * NT + tg];
            if (t >= 1) loc += tr[lb[t - 1] * NT + tg];
        }
    }
    red[tid] = loc;
    __syncthreads();
    if (tid == 0) {
        float score = 0.f;
        for (int i = 0; i < 64; ++i) score += red[i];
        score += st[lb[0]] + et[lb[L - 1]];
        float m = -1e30f;
        for (int j = 0; j < NT; ++j) m = fmaxf(m, alpha[p][j] + et[j]);
        float s = 0.f;
        for (int j = 0; j < NT; ++j) s += __expf(alpha[p][j] + et[j] - m);
        float logz = m + __logf(s);
        g_res[b] = score - logz;
    }
}

__global__ void final_kernel(float* __restrict__ out) {
    if (threadIdx.x == 0) {
        float s = 0.f;
        for (int b = 0; b < NB; ++b) s += g_res[b];
        out[0] = -s;
    }
}

extern "C" void kernel_launch(void* const* d_in, const int* in_sizes, int n_in,
                              void* d_out, int out_size)
{
    (void)in_sizes; (void)n_in; (void)out_size;
    const int*   tok    = (const int*)d_in[0];
    const int*   seql   = (const int*)d_in[1];
    const int*   labels = (const int*)d_in[2];
    const float* emb    = (const float*)d_in[3];
    const float* wihf   = (const float*)d_in[4];
    const float* whhf   = (const float*)d_in[5];
    const float* bihf   = (const float*)d_in[6];
    const float* bhhf   = (const float*)d_in[7];
    const float* wihb   = (const float*)d_in[8];
    const float* whhb   = (const float*)d_in[9];
    const float* bihb   = (const float*)d_in[10];
    const float* bhhb   = (const float*)d_in[11];
    const float* wlin   = (const float*)d_in[12];
    const float* blin   = (const float*)d_in[13];
    const float* trans  = (const float*)d_in[14];
    const float* st     = (const float*)d_in[15];
    const float* et     = (const float*)d_in[16];
    float* out = (float*)d_out;

    cudaFuncSetAttribute(lstm_kernel,   cudaFuncAttributeMaxDynamicSharedMemorySize, LSTM_SMEM);
    cudaFuncSetAttribute(logits_kernel, cudaFuncAttributeMaxDynamicSharedMemorySize, LOGITS_SMEM);

    conv_whh_kernel<<<(2 * 131072 + 255) / 256, 256>>>(whhf, whhb);
    dim3 g1(512, 32);
    input_gemm_kernel<<<g1, 256>>>(tok, emb, wihf, wihb, bihf, bhhf, bihb, bhhb);
    init_bar_kernel<<<1, 32>>>();
    lstm_kernel<<<128, 256, LSTM_SMEM>>>();
    logits_kernel<<<1024, 256, LOGITS_SMEM>>>(wlin, blin);
    crf_kernel<<<64, 64>>>(labels, seql, trans, st, et);
    final_kernel<<<1, 32>>>(out);
}